// round 1
// baseline (speedup 1.0000x reference)
#include <cuda_runtime.h>
#include <math.h>

#define BATCH 1024

// ----------------------------------------------------------------------------
// Scratch (device globals; allocation-free per harness rules)
// ----------------------------------------------------------------------------
__device__ float g_st[BATCH * 129];          // [t, x] per row, stride 129
__device__ float g_h1[BATCH * 1024];
__device__ float g_h2[BATCH * 960];
__device__ float g_h3[BATCH * 896];
__device__ float g_e1[BATCH * 512];
__device__ float g_e2[BATCH * 448];
__device__ float g_gv[BATCH];
__device__ float g_t2[(size_t)BATCH * 128 * 960];   // tangent after layer 2 (i padded to 128)
__device__ float g_trp[BATCH * 8];                  // partial traces (7 c-tiles used)

// ----------------------------------------------------------------------------
// Build st = concat([pseudo_t, x], axis=1), stride 129.
// z = concat([pseudo_t, x[:, :127]]) is simply st[:, :128].
// ----------------------------------------------------------------------------
__global__ void k_build(const float* __restrict__ t, const float* __restrict__ x)
{
    int i = blockIdx.x * blockDim.x + threadIdx.x;
    if (i >= BATCH * 129) return;
    int b = i / 129, j = i % 129;
    g_st[i] = (j == 0) ? t[0] : x[b * 128 + (j - 1)];
}

// ----------------------------------------------------------------------------
// Generic fp32 GEMM: C = act(A[M,K](lda) @ W[K,N] + bias), 64x64x16 tiles.
// ACT: 0 = none, 1 = tanh
// ----------------------------------------------------------------------------
template <int ACT>
__global__ void gemm64(const float* __restrict__ Amat, int lda,
                       const float* __restrict__ Wmat,
                       const float* __restrict__ bias,
                       float* __restrict__ C, int ldc,
                       int M, int N, int K)
{
    __shared__ float As[64][17];
    __shared__ float Bs[16][65];
    int tid = threadIdx.x;
    int tx = tid & 15, ty = tid >> 4;
    int row0 = blockIdx.y * 64, col0 = blockIdx.x * 64;
    float acc[4][4] = {};

    for (int k0 = 0; k0 < K; k0 += 16) {
        #pragma unroll
        for (int q = 0; q < 4; q++) {
            int idx = tid * 4 + q;
            int r = idx >> 4, c = idx & 15;
            int gr = row0 + r, gk = k0 + c;
            As[r][c] = (gr < M && gk < K) ? Amat[(size_t)gr * lda + gk] : 0.f;
        }
        #pragma unroll
        for (int q = 0; q < 4; q++) {
            int idx = tid * 4 + q;
            int r = idx >> 6, c = idx & 63;
            int gk = k0 + r, gc = col0 + c;
            Bs[r][c] = (gk < K && gc < N) ? Wmat[(size_t)gk * N + gc] : 0.f;
        }
        __syncthreads();
        #pragma unroll
        for (int kk = 0; kk < 16; kk++) {
            float a[4], bv[4];
            #pragma unroll
            for (int m = 0; m < 4; m++) a[m] = As[ty * 4 + m][kk];
            #pragma unroll
            for (int n = 0; n < 4; n++) bv[n] = Bs[kk][tx * 4 + n];
            #pragma unroll
            for (int m = 0; m < 4; m++)
                #pragma unroll
                for (int n = 0; n < 4; n++) acc[m][n] += a[m] * bv[n];
        }
        __syncthreads();
    }
    #pragma unroll
    for (int m = 0; m < 4; m++) {
        int gr = row0 + ty * 4 + m;
        if (gr >= M) continue;
        #pragma unroll
        for (int n = 0; n < 4; n++) {
            int gc = col0 + tx * 4 + n;
            if (gc >= N) continue;
            float v = acc[m][n] + bias[gc];
            if (ACT) v = tanhf(v);
            C[(size_t)gr * ldc + gc] = v;
        }
    }
}

// ----------------------------------------------------------------------------
// Jacobian stage 1: t2[b, i, j] = d2[b,j] * sum_a gw0[i+1,a]*d1[b,a]*gw1[a,j]
// One CTA = (one sample b) x (128-col j tile). 128x128x8 tile, 8x8 microtile.
// Row i=127 is zero padding (only 127 tangents).
// ----------------------------------------------------------------------------
__global__ void kJ1(const float* __restrict__ gw0, const float* __restrict__ gw1)
{
    int b = blockIdx.y;
    int col0 = blockIdx.x * 128;               // 8 tiles over 960 (last partial)
    __shared__ __align__(16) float As[8][132]; // As[k][i]
    __shared__ __align__(16) float Bs[8][132]; // Bs[k][j]
    const float* h1b = g_h1 + (size_t)b * 1024;
    int tid = threadIdx.x;
    int tx = tid & 15, ty = tid >> 4;
    float acc[8][8] = {};

    for (int k0 = 0; k0 < 1024; k0 += 8) {
        #pragma unroll
        for (int q = 0; q < 4; q++) {
            int idx = tid * 4 + q;
            int i = idx >> 3, k = idx & 7;
            float v = 0.f;
            if (i < 127) {
                float h = h1b[k0 + k];
                v = gw0[(size_t)(i + 1) * 1024 + k0 + k] * (1.f - h * h);
            }
            As[k][i] = v;
        }
        #pragma unroll
        for (int q = 0; q < 4; q++) {
            int idx = tid * 4 + q;
            int k = idx >> 7, j = idx & 127;
            int gj = col0 + j;
            Bs[k][j] = (gj < 960) ? gw1[(size_t)(k0 + k) * 960 + gj] : 0.f;
        }
        __syncthreads();
        #pragma unroll
        for (int kk = 0; kk < 8; kk++) {
            float4 a0 = *(const float4*)&As[kk][ty * 8];
            float4 a1 = *(const float4*)&As[kk][ty * 8 + 4];
            float4 b0 = *(const float4*)&Bs[kk][tx * 8];
            float4 b1 = *(const float4*)&Bs[kk][tx * 8 + 4];
            float a[8] = {a0.x, a0.y, a0.z, a0.w, a1.x, a1.y, a1.z, a1.w};
            float bv[8] = {b0.x, b0.y, b0.z, b0.w, b1.x, b1.y, b1.z, b1.w};
            #pragma unroll
            for (int m = 0; m < 8; m++)
                #pragma unroll
                for (int n = 0; n < 8; n++) acc[m][n] += a[m] * bv[n];
        }
        __syncthreads();
    }
    const float* h2b = g_h2 + (size_t)b * 960;
    float* t2b = g_t2 + (size_t)b * 128 * 960;
    #pragma unroll
    for (int n = 0; n < 8; n++) {
        int gj = col0 + tx * 8 + n;
        if (gj >= 960) continue;
        float h = h2b[gj];
        float d2 = 1.f - h * h;
        #pragma unroll
        for (int m = 0; m < 8; m++) {
            int i = ty * 8 + m;
            t2b[(size_t)i * 960 + gj] = acc[m][n] * d2;
        }
    }
}

// ----------------------------------------------------------------------------
// Jacobian stage 2 + trace contraction:
//   t3[i,c] = sum_j t2[b,i,j] * gw2[j,c]
//   partial_tr[b,ctile] = sum_{i,c in tile} t3[i,c] * d3[b,c] * gdw[c,i]
// One CTA = (sample b) x (128-col c tile); 7 tiles cover 896 exactly.
// ----------------------------------------------------------------------------
__global__ void kJ2(const float* __restrict__ gw2, const float* __restrict__ gdw)
{
    int b = blockIdx.y;
    int c0 = blockIdx.x * 128;
    __shared__ __align__(16) float As[8][132]; // t2 tile, As[k][i]
    __shared__ __align__(16) float Bs[8][132]; // gw2 tile, Bs[k][c]
    const float* t2b = g_t2 + (size_t)b * 128 * 960;
    int tid = threadIdx.x;
    int tx = tid & 15, ty = tid >> 4;
    float acc[8][8] = {};

    for (int k0 = 0; k0 < 960; k0 += 8) {
        #pragma unroll
        for (int q = 0; q < 4; q++) {
            int idx = tid * 4 + q;
            int i = idx >> 3, k = idx & 7;
            As[k][i] = t2b[(size_t)i * 960 + k0 + k];
        }
        #pragma unroll
        for (int q = 0; q < 4; q++) {
            int idx = tid * 4 + q;
            int k = idx >> 7, c = idx & 127;
            Bs[k][c] = gw2[(size_t)(k0 + k) * 896 + c0 + c];
        }
        __syncthreads();
        #pragma unroll
        for (int kk = 0; kk < 8; kk++) {
            float4 a0 = *(const float4*)&As[kk][ty * 8];
            float4 a1 = *(const float4*)&As[kk][ty * 8 + 4];
            float4 b0 = *(const float4*)&Bs[kk][tx * 8];
            float4 b1 = *(const float4*)&Bs[kk][tx * 8 + 4];
            float a[8] = {a0.x, a0.y, a0.z, a0.w, a1.x, a1.y, a1.z, a1.w};
            float bv[8] = {b0.x, b0.y, b0.z, b0.w, b1.x, b1.y, b1.z, b1.w};
            #pragma unroll
            for (int m = 0; m < 8; m++)
                #pragma unroll
                for (int n = 0; n < 8; n++) acc[m][n] += a[m] * bv[n];
        }
        __syncthreads();
    }
    const float* h3b = g_h3 + (size_t)b * 896;
    float s = 0.f;
    #pragma unroll
    for (int n = 0; n < 8; n++) {
        int c = c0 + tx * 8 + n;
        float h = h3b[c];
        float d3 = 1.f - h * h;
        #pragma unroll
        for (int m = 0; m < 8; m++) {
            int i = ty * 8 + m;   // i=127 contributes 0 (t2 row zeroed)
            s += acc[m][n] * d3 * gdw[(size_t)c * 128 + i];
        }
    }
    __shared__ float red[256];
    red[tid] = s;
    __syncthreads();
    for (int st = 128; st > 0; st >>= 1) {
        if (tid < st) red[tid] += red[tid + st];
        __syncthreads();
    }
    if (tid == 0) g_trp[b * 8 + blockIdx.x] = red[0];
}

// ----------------------------------------------------------------------------
// g[b] = e2[b,:] @ bdw + bdb  (GEMV, one block per sample)
// ----------------------------------------------------------------------------
__global__ void kGemv(const float* __restrict__ bdw, const float* __restrict__ bdb,
                      float* __restrict__ out)
{
    int b = blockIdx.x;
    int tid = threadIdx.x; // 128 threads
    const float* e = g_e2 + (size_t)b * 448;
    float s = 0.f;
    for (int k = tid; k < 448; k += 128) s += e[k] * bdw[k];
    __shared__ float red[128];
    red[tid] = s;
    __syncthreads();
    for (int st = 64; st > 0; st >>= 1) {
        if (tid < st) red[tid] += red[tid + st];
        __syncthreads();
    }
    if (tid == 0) {
        float gv = red[0] + bdb[0];
        g_gv[b] = gv;
        out[131072 + b] = gv;
    }
}

// ----------------------------------------------------------------------------
// dp_dt[b] = g[b] - p[b] * tr[b]
// ----------------------------------------------------------------------------
__global__ void kFinal(const float* __restrict__ p, float* __restrict__ out)
{
    int b = blockIdx.x * blockDim.x + threadIdx.x;
    if (b >= BATCH) return;
    float tr = 0.f;
    #pragma unroll
    for (int t = 0; t < 7; t++) tr += g_trp[b * 8 + t];
    out[132096 + b] = g_gv[b] - p[b] * tr;
}

// ----------------------------------------------------------------------------
extern "C" void kernel_launch(void* const* d_in, const int* in_sizes, int n_in,
                              void* d_out, int out_size)
{
    const float* t   = (const float*)d_in[0];
    const float* x   = (const float*)d_in[1];
    // d_in[2] = g_x (unused by reference)
    const float* p   = (const float*)d_in[3];
    const float* gw0 = (const float*)d_in[4];
    const float* gb0 = (const float*)d_in[5];
    const float* gw1 = (const float*)d_in[6];
    const float* gb1 = (const float*)d_in[7];
    const float* gw2 = (const float*)d_in[8];
    const float* gb2 = (const float*)d_in[9];
    const float* gdw = (const float*)d_in[10];
    const float* gdb = (const float*)d_in[11];
    const float* bw0 = (const float*)d_in[12];
    const float* bb0 = (const float*)d_in[13];
    const float* bw1 = (const float*)d_in[14];
    const float* bb1 = (const float*)d_in[15];
    const float* bdw = (const float*)d_in[16];
    const float* bdb = (const float*)d_in[17];
    float* out = (float*)d_out;

    float *st, *h1, *h2, *h3, *e1, *e2;
    cudaGetSymbolAddress((void**)&st, g_st);
    cudaGetSymbolAddress((void**)&h1, g_h1);
    cudaGetSymbolAddress((void**)&h2, g_h2);
    cudaGetSymbolAddress((void**)&h3, g_h3);
    cudaGetSymbolAddress((void**)&e1, g_e1);
    cudaGetSymbolAddress((void**)&e2, g_e2);

    // Build st
    k_build<<<(BATCH * 129 + 255) / 256, 256>>>(t, x);

    // grn forward (z = st[:, :128], lda=129)
    gemm64<1><<<dim3(16, 16), 256>>>(st, 129, gw0, gb0, h1, 1024, 1024, 1024, 128);
    gemm64<1><<<dim3(15, 16), 256>>>(h1, 1024, gw1, gb1, h2, 960, 1024, 960, 1024);
    gemm64<1><<<dim3(14, 16), 256>>>(h2, 960, gw2, gb2, h3, 896, 1024, 896, 960);
    // dx_dt -> out[0 : 131072]
    gemm64<0><<<dim3(2, 16), 256>>>(h3, 896, gdw, gdb, out, 128, 1024, 128, 896);

    // b-network forward
    gemm64<1><<<dim3(8, 16), 256>>>(st, 129, bw0, bb0, e1, 512, 1024, 512, 129);
    gemm64<1><<<dim3(7, 16), 256>>>(e1, 512, bw1, bb1, e2, 448, 1024, 448, 512);
    kGemv<<<BATCH, 128>>>(bdw, bdb, out);

    // Jacobian trace
    kJ1<<<dim3(8, BATCH), 256>>>(gw0, gw1);
    kJ2<<<dim3(7, BATCH), 256>>>(gw2, gdw);
    kFinal<<<4, 256>>>(p, out);

    (void)in_sizes; (void)n_in; (void)out_size;
}

// round 2
// speedup vs baseline: 1.0014x; 1.0014x over previous
#include <cuda_runtime.h>
#include <math.h>

#define BATCH 1024

// ----------------------------------------------------------------------------
// Scratch (device globals; allocation-free per harness rules)
// ----------------------------------------------------------------------------
__device__ float g_st[BATCH * 129];          // [t, x] per row, stride 129
__device__ float g_h1[BATCH * 1024];
__device__ float g_h2[BATCH * 960];
__device__ float g_h3[BATCH * 896];
__device__ float g_e1[BATCH * 512];
__device__ float g_e2[BATCH * 448];
__device__ float g_gv[BATCH];
__device__ float g_t2[(size_t)BATCH * 128 * 960];   // tangent after layer 2 (i padded to 128)
__device__ float g_trp[BATCH * 8];                  // partial traces (7 c-tiles used)

// ----------------------------------------------------------------------------
// Build st = concat([pseudo_t, x], axis=1), stride 129.
// z = concat([pseudo_t, x[:, :127]]) is simply st[:, :128].
// ----------------------------------------------------------------------------
__global__ void k_build(const float* __restrict__ t, const float* __restrict__ x)
{
    int i = blockIdx.x * blockDim.x + threadIdx.x;
    if (i >= BATCH * 129) return;
    int b = i / 129, j = i % 129;
    g_st[i] = (j == 0) ? t[0] : x[b * 128 + (j - 1)];
}

// ----------------------------------------------------------------------------
// Generic fp32 GEMM: C = act(A[M,K](lda) @ W[K,N] + bias), 64x64x16 tiles.
// ACT: 0 = none, 1 = tanh
// ----------------------------------------------------------------------------
template <int ACT>
__global__ void gemm64(const float* __restrict__ Amat, int lda,
                       const float* __restrict__ Wmat,
                       const float* __restrict__ bias,
                       float* __restrict__ C, int ldc,
                       int M, int N, int K)
{
    __shared__ float As[64][17];
    __shared__ float Bs[16][65];
    int tid = threadIdx.x;
    int tx = tid & 15, ty = tid >> 4;
    int row0 = blockIdx.y * 64, col0 = blockIdx.x * 64;
    float acc[4][4] = {};

    for (int k0 = 0; k0 < K; k0 += 16) {
        #pragma unroll
        for (int q = 0; q < 4; q++) {
            int idx = tid * 4 + q;
            int r = idx >> 4, c = idx & 15;
            int gr = row0 + r, gk = k0 + c;
            As[r][c] = (gr < M && gk < K) ? Amat[(size_t)gr * lda + gk] : 0.f;
        }
        #pragma unroll
        for (int q = 0; q < 4; q++) {
            int idx = tid * 4 + q;
            int r = idx >> 6, c = idx & 63;
            int gk = k0 + r, gc = col0 + c;
            Bs[r][c] = (gk < K && gc < N) ? Wmat[(size_t)gk * N + gc] : 0.f;
        }
        __syncthreads();
        #pragma unroll
        for (int kk = 0; kk < 16; kk++) {
            float a[4], bv[4];
            #pragma unroll
            for (int m = 0; m < 4; m++) a[m] = As[ty * 4 + m][kk];
            #pragma unroll
            for (int n = 0; n < 4; n++) bv[n] = Bs[kk][tx * 4 + n];
            #pragma unroll
            for (int m = 0; m < 4; m++)
                #pragma unroll
                for (int n = 0; n < 4; n++) acc[m][n] += a[m] * bv[n];
        }
        __syncthreads();
    }
    #pragma unroll
    for (int m = 0; m < 4; m++) {
        int gr = row0 + ty * 4 + m;
        if (gr >= M) continue;
        #pragma unroll
        for (int n = 0; n < 4; n++) {
            int gc = col0 + tx * 4 + n;
            if (gc >= N) continue;
            float v = acc[m][n] + bias[gc];
            if (ACT) v = tanhf(v);
            C[(size_t)gr * ldc + gc] = v;
        }
    }
}

// ----------------------------------------------------------------------------
// Jacobian stage 1: t2[b, i, j] = d2[b,j] * sum_a gw0[i+1,a]*d1[b,a]*gw1[a,j]
// One CTA = (one sample b) x (128-col j tile). 128x128x8 tile, 8x8 microtile.
// Row i=127 is zero padding (only 127 tangents).
// ----------------------------------------------------------------------------
__global__ void kJ1(const float* __restrict__ gw0, const float* __restrict__ gw1)
{
    int b = blockIdx.y;
    int col0 = blockIdx.x * 128;               // 8 tiles over 960 (last partial)
    __shared__ __align__(16) float As[8][132]; // As[k][i]
    __shared__ __align__(16) float Bs[8][132]; // Bs[k][j]
    const float* h1b = g_h1 + (size_t)b * 1024;
    int tid = threadIdx.x;
    int tx = tid & 15, ty = tid >> 4;
    float acc[8][8] = {};

    for (int k0 = 0; k0 < 1024; k0 += 8) {
        #pragma unroll
        for (int q = 0; q < 4; q++) {
            int idx = tid * 4 + q;
            int i = idx >> 3, k = idx & 7;
            float v = 0.f;
            if (i < 127) {
                float h = h1b[k0 + k];
                v = gw0[(size_t)(i + 1) * 1024 + k0 + k] * (1.f - h * h);
            }
            As[k][i] = v;
        }
        #pragma unroll
        for (int q = 0; q < 4; q++) {
            int idx = tid * 4 + q;
            int k = idx >> 7, j = idx & 127;
            int gj = col0 + j;
            Bs[k][j] = (gj < 960) ? gw1[(size_t)(k0 + k) * 960 + gj] : 0.f;
        }
        __syncthreads();
        #pragma unroll
        for (int kk = 0; kk < 8; kk++) {
            float4 a0 = *(const float4*)&As[kk][ty * 8];
            float4 a1 = *(const float4*)&As[kk][ty * 8 + 4];
            float4 b0 = *(const float4*)&Bs[kk][tx * 8];
            float4 b1 = *(const float4*)&Bs[kk][tx * 8 + 4];
            float a[8] = {a0.x, a0.y, a0.z, a0.w, a1.x, a1.y, a1.z, a1.w};
            float bv[8] = {b0.x, b0.y, b0.z, b0.w, b1.x, b1.y, b1.z, b1.w};
            #pragma unroll
            for (int m = 0; m < 8; m++)
                #pragma unroll
                for (int n = 0; n < 8; n++) acc[m][n] += a[m] * bv[n];
        }
        __syncthreads();
    }
    const float* h2b = g_h2 + (size_t)b * 960;
    float* t2b = g_t2 + (size_t)b * 128 * 960;
    #pragma unroll
    for (int n = 0; n < 8; n++) {
        int gj = col0 + tx * 8 + n;
        if (gj >= 960) continue;
        float h = h2b[gj];
        float d2 = 1.f - h * h;
        #pragma unroll
        for (int m = 0; m < 8; m++) {
            int i = ty * 8 + m;
            t2b[(size_t)i * 960 + gj] = acc[m][n] * d2;
        }
    }
}

// ----------------------------------------------------------------------------
// Jacobian stage 2 + trace contraction:
//   t3[i,c] = sum_j t2[b,i,j] * gw2[j,c]
//   partial_tr[b,ctile] = sum_{i,c in tile} t3[i,c] * d3[b,c] * gdw[c,i]
// One CTA = (sample b) x (128-col c tile); 7 tiles cover 896 exactly.
// ----------------------------------------------------------------------------
__global__ void kJ2(const float* __restrict__ gw2, const float* __restrict__ gdw)
{
    int b = blockIdx.y;
    int c0 = blockIdx.x * 128;
    __shared__ __align__(16) float As[8][132]; // t2 tile, As[k][i]
    __shared__ __align__(16) float Bs[8][132]; // gw2 tile, Bs[k][c]
    const float* t2b = g_t2 + (size_t)b * 128 * 960;
    int tid = threadIdx.x;
    int tx = tid & 15, ty = tid >> 4;
    float acc[8][8] = {};

    for (int k0 = 0; k0 < 960; k0 += 8) {
        #pragma unroll
        for (int q = 0; q < 4; q++) {
            int idx = tid * 4 + q;
            int i = idx >> 3, k = idx & 7;
            As[k][i] = t2b[(size_t)i * 960 + k0 + k];
        }
        #pragma unroll
        for (int q = 0; q < 4; q++) {
            int idx = tid * 4 + q;
            int k = idx >> 7, c = idx & 127;
            Bs[k][c] = gw2[(size_t)(k0 + k) * 896 + c0 + c];
        }
        __syncthreads();
        #pragma unroll
        for (int kk = 0; kk < 8; kk++) {
            float4 a0 = *(const float4*)&As[kk][ty * 8];
            float4 a1 = *(const float4*)&As[kk][ty * 8 + 4];
            float4 b0 = *(const float4*)&Bs[kk][tx * 8];
            float4 b1 = *(const float4*)&Bs[kk][tx * 8 + 4];
            float a[8] = {a0.x, a0.y, a0.z, a0.w, a1.x, a1.y, a1.z, a1.w};
            float bv[8] = {b0.x, b0.y, b0.z, b0.w, b1.x, b1.y, b1.z, b1.w};
            #pragma unroll
            for (int m = 0; m < 8; m++)
                #pragma unroll
                for (int n = 0; n < 8; n++) acc[m][n] += a[m] * bv[n];
        }
        __syncthreads();
    }
    const float* h3b = g_h3 + (size_t)b * 896;
    float s = 0.f;
    #pragma unroll
    for (int n = 0; n < 8; n++) {
        int c = c0 + tx * 8 + n;
        float h = h3b[c];
        float d3 = 1.f - h * h;
        #pragma unroll
        for (int m = 0; m < 8; m++) {
            int i = ty * 8 + m;   // i=127 contributes 0 (t2 row zeroed)
            s += acc[m][n] * d3 * gdw[(size_t)c * 128 + i];
        }
    }
    __shared__ float red[256];
    red[tid] = s;
    __syncthreads();
    for (int st = 128; st > 0; st >>= 1) {
        if (tid < st) red[tid] += red[tid + st];
        __syncthreads();
    }
    if (tid == 0) g_trp[b * 8 + blockIdx.x] = red[0];
}

// ----------------------------------------------------------------------------
// g[b] = e2[b,:] @ bdw + bdb  (GEMV, one block per sample)
// ----------------------------------------------------------------------------
__global__ void kGemv(const float* __restrict__ bdw, const float* __restrict__ bdb,
                      float* __restrict__ out)
{
    int b = blockIdx.x;
    int tid = threadIdx.x; // 128 threads
    const float* e = g_e2 + (size_t)b * 448;
    float s = 0.f;
    for (int k = tid; k < 448; k += 128) s += e[k] * bdw[k];
    __shared__ float red[128];
    red[tid] = s;
    __syncthreads();
    for (int st = 64; st > 0; st >>= 1) {
        if (tid < st) red[tid] += red[tid + st];
        __syncthreads();
    }
    if (tid == 0) {
        float gv = red[0] + bdb[0];
        g_gv[b] = gv;
        out[131072 + b] = gv;
    }
}

// ----------------------------------------------------------------------------
// dp_dt[b] = g[b] - p[b] * tr[b]
// ----------------------------------------------------------------------------
__global__ void kFinal(const float* __restrict__ p, float* __restrict__ out)
{
    int b = blockIdx.x * blockDim.x + threadIdx.x;
    if (b >= BATCH) return;
    float tr = 0.f;
    #pragma unroll
    for (int t = 0; t < 7; t++) tr += g_trp[b * 8 + t];
    out[132096 + b] = g_gv[b] - p[b] * tr;
}

// ----------------------------------------------------------------------------
extern "C" void kernel_launch(void* const* d_in, const int* in_sizes, int n_in,
                              void* d_out, int out_size)
{
    const float* t   = (const float*)d_in[0];
    const float* x   = (const float*)d_in[1];
    // d_in[2] = g_x (unused by reference)
    const float* p   = (const float*)d_in[3];
    const float* gw0 = (const float*)d_in[4];
    const float* gb0 = (const float*)d_in[5];
    const float* gw1 = (const float*)d_in[6];
    const float* gb1 = (const float*)d_in[7];
    const float* gw2 = (const float*)d_in[8];
    const float* gb2 = (const float*)d_in[9];
    const float* gdw = (const float*)d_in[10];
    const float* gdb = (const float*)d_in[11];
    const float* bw0 = (const float*)d_in[12];
    const float* bb0 = (const float*)d_in[13];
    const float* bw1 = (const float*)d_in[14];
    const float* bb1 = (const float*)d_in[15];
    const float* bdw = (const float*)d_in[16];
    const float* bdb = (const float*)d_in[17];
    float* out = (float*)d_out;

    float *st, *h1, *h2, *h3, *e1, *e2;
    cudaGetSymbolAddress((void**)&st, g_st);
    cudaGetSymbolAddress((void**)&h1, g_h1);
    cudaGetSymbolAddress((void**)&h2, g_h2);
    cudaGetSymbolAddress((void**)&h3, g_h3);
    cudaGetSymbolAddress((void**)&e1, g_e1);
    cudaGetSymbolAddress((void**)&e2, g_e2);

    // Build st
    k_build<<<(BATCH * 129 + 255) / 256, 256>>>(t, x);

    // grn forward (z = st[:, :128], lda=129)
    gemm64<1><<<dim3(16, 16), 256>>>(st, 129, gw0, gb0, h1, 1024, 1024, 1024, 128);
    gemm64<1><<<dim3(15, 16), 256>>>(h1, 1024, gw1, gb1, h2, 960, 1024, 960, 1024);
    gemm64<1><<<dim3(14, 16), 256>>>(h2, 960, gw2, gb2, h3, 896, 1024, 896, 960);
    // dx_dt -> out[0 : 131072]
    gemm64<0><<<dim3(2, 16), 256>>>(h3, 896, gdw, gdb, out, 128, 1024, 128, 896);

    // b-network forward
    gemm64<1><<<dim3(8, 16), 256>>>(st, 129, bw0, bb0, e1, 512, 1024, 512, 129);
    gemm64<1><<<dim3(7, 16), 256>>>(e1, 512, bw1, bb1, e2, 448, 1024, 448, 512);
    kGemv<<<BATCH, 128>>>(bdw, bdb, out);

    // Jacobian trace
    kJ1<<<dim3(8, BATCH), 256>>>(gw0, gw1);
    kJ2<<<dim3(7, BATCH), 256>>>(gw2, gdw);
    kFinal<<<4, 256>>>(p, out);

    (void)in_sizes; (void)n_in; (void)out_size;
}

// round 7
// speedup vs baseline: 2.9510x; 2.9467x over previous
#include <cuda_runtime.h>
#include <cuda_bf16.h>
#include <math.h>
#include <stdint.h>

#define BATCH 1024

// ---------------- scratch globals ----------------
__device__ float g_st[BATCH * 129];
__device__ float g_h1[BATCH * 1024];
__device__ float g_h2[BATCH * 960];
__device__ float g_h3[BATCH * 896];
__device__ float g_e1[BATCH * 512];
__device__ float g_e2[BATCH * 448];
__device__ float g_gv[BATCH];
__device__ unsigned int g_t2p[(size_t)BATCH * 128 * 960]; // packed hi|lo<<16 bf16, [b][i][j]
__device__ float g_trp[BATCH * 16];
// pre-swizzled transposed bf16 B operands: [kchunk][row][64]
__device__ __nv_bfloat16 g_b1h[16 * 960 * 64];   // B1'[j][a] tiles
__device__ __nv_bfloat16 g_b1l[16 * 960 * 64];
__device__ __nv_bfloat16 g_b2h[15 * 896 * 64];   // B2'[c][j] tiles
__device__ __nv_bfloat16 g_b2l[15 * 896 * 64];

// ---------------- helpers ----------------
__device__ __forceinline__ uint32_t smem_u32(const void* p) {
    uint32_t a;
    asm("{ .reg .u64 t; cvta.to.shared.u64 t, %1; cvt.u32.u64 %0, t; }" : "=r"(a) : "l"(p));
    return a;
}
__device__ __forceinline__ void ldm_x4(uint32_t* r, uint32_t addr) {
    asm volatile("ldmatrix.sync.aligned.m8n8.x4.shared.b16 {%0,%1,%2,%3}, [%4];"
        : "=r"(r[0]), "=r"(r[1]), "=r"(r[2]), "=r"(r[3]) : "r"(addr));
}
__device__ __forceinline__ void mma16816(float* d, const uint32_t* a, uint32_t b0, uint32_t b1) {
    asm volatile("mma.sync.aligned.m16n8k16.row.col.f32.bf16.bf16.f32 "
        "{%0,%1,%2,%3}, {%4,%5,%6,%7}, {%8,%9}, {%0,%1,%2,%3};"
        : "+f"(d[0]), "+f"(d[1]), "+f"(d[2]), "+f"(d[3])
        : "r"(a[0]), "r"(a[1]), "r"(a[2]), "r"(a[3]), "r"(b0), "r"(b1));
}
__device__ __forceinline__ void cpa16(uint32_t dst, const void* src) {
    asm volatile("cp.async.cg.shared.global [%0], [%1], 16;" :: "r"(dst), "l"(src));
}
#define CP_COMMIT() asm volatile("cp.async.commit_group;" ::: "memory")
#define CP_WAIT(n)  asm volatile("cp.async.wait_group %0;" :: "n"(n) : "memory")

__device__ __forceinline__ uint32_t pack_hilo(float v) {
    __nv_bfloat16 h = __float2bfloat16(v);
    __nv_bfloat16 l = __float2bfloat16(v - __bfloat162float(h));
    return (uint32_t)__bfloat16_as_ushort(h) | ((uint32_t)__bfloat16_as_ushort(l) << 16);
}
__device__ __forceinline__ void split2(float v0, float v1, uint32_t& hi, uint32_t& lo) {
    uint32_t p0 = pack_hilo(v0), p1 = pack_hilo(v1);
    hi = (p0 & 0xFFFFu) | (p1 << 16);
    lo = (p0 >> 16) | (p1 & 0xFFFF0000u);
}

// ---------------- misc kernels ----------------
__global__ void k_build(const float* __restrict__ t, const float* __restrict__ x)
{
    int i = blockIdx.x * blockDim.x + threadIdx.x;
    if (i >= BATCH * 129) return;
    int b = i / 129, j = i % 129;
    g_st[i] = (j == 0) ? t[0] : x[b * 128 + (j - 1)];
}
// B1'[j][a] = gw1[a][j], tiled [ac][j][64], xor-swizzled, output-major
__global__ void kPrepB1(const float* __restrict__ gw1)
{
    int idx = blockIdx.x * blockDim.x + threadIdx.x;
    if (idx >= 16 * 960 * 64) return;
    int ac = idx / (960 * 64);
    int r = idx % (960 * 64);
    int j = r / 64, e = r % 64;
    int a = ac * 64 + (e ^ ((j & 7) << 3));
    float v = gw1[(size_t)a * 960 + j];
    __nv_bfloat16 h = __float2bfloat16(v);
    g_b1h[idx] = h;
    g_b1l[idx] = __float2bfloat16(v - __bfloat162float(h));
}
// B2'[c][j] = gw2[j][c], tiled [jc][c][64]
__global__ void kPrepB2(const float* __restrict__ gw2)
{
    int idx = blockIdx.x * blockDim.x + threadIdx.x;
    if (idx >= 15 * 896 * 64) return;
    int jc = idx / (896 * 64);
    int r = idx % (896 * 64);
    int c = r / 64, e = r % 64;
    int j = jc * 64 + (e ^ ((c & 7) << 3));
    float v = gw2[(size_t)j * 896 + c];
    __nv_bfloat16 h = __float2bfloat16(v);
    g_b2h[idx] = h;
    g_b2l[idx] = __float2bfloat16(v - __bfloat162float(h));
}

// ---------------- fp32 forward GEMM (R1, unchanged) ----------------
template <int ACT>
__global__ void gemm64(const float* __restrict__ Amat, int lda,
                       const float* __restrict__ Wmat, const float* __restrict__ bias,
                       float* __restrict__ C, int ldc, int M, int N, int K)
{
    __shared__ float As[64][17];
    __shared__ float Bs[16][65];
    int tid = threadIdx.x, tx = tid & 15, ty = tid >> 4;
    int row0 = blockIdx.y * 64, col0 = blockIdx.x * 64;
    float acc[4][4] = {};
    for (int k0 = 0; k0 < K; k0 += 16) {
        #pragma unroll
        for (int q = 0; q < 4; q++) {
            int idx = tid * 4 + q, r = idx >> 4, c = idx & 15;
            int gr = row0 + r, gk = k0 + c;
            As[r][c] = (gr < M && gk < K) ? Amat[(size_t)gr * lda + gk] : 0.f;
        }
        #pragma unroll
        for (int q = 0; q < 4; q++) {
            int idx = tid * 4 + q, r = idx >> 6, c = idx & 63;
            int gk = k0 + r, gc = col0 + c;
            Bs[r][c] = (gk < K && gc < N) ? Wmat[(size_t)gk * N + gc] : 0.f;
        }
        __syncthreads();
        #pragma unroll
        for (int kk = 0; kk < 16; kk++) {
            float a[4], bv[4];
            #pragma unroll
            for (int m = 0; m < 4; m++) a[m] = As[ty * 4 + m][kk];
            #pragma unroll
            for (int n = 0; n < 4; n++) bv[n] = Bs[kk][tx * 4 + n];
            #pragma unroll
            for (int m = 0; m < 4; m++)
                #pragma unroll
                for (int n = 0; n < 4; n++) acc[m][n] += a[m] * bv[n];
        }
        __syncthreads();
    }
    #pragma unroll
    for (int m = 0; m < 4; m++) {
        int gr = row0 + ty * 4 + m;
        if (gr >= M) continue;
        #pragma unroll
        for (int n = 0; n < 4; n++) {
            int gc = col0 + tx * 4 + n;
            if (gc >= N) continue;
            float v = acc[m][n] + bias[gc];
            if (ACT) v = tanhf(v);
            C[(size_t)gr * ldc + gc] = v;
        }
    }
}

// ============================================================================
// Stage 1 (mma.sync): D[i,j] = sum_a (gw0[i+1,a]*d1[b,a]) * gw1[a,j]
// grid (15, 1024): 64-wide j tiles. K = 1024 = 16 chunks of 64. 3-pass bf16.
// Epilogue: *d2[j], pack hi/lo -> g_t2p[b][i][j].
// smem layout per buffer: Ah(16384) Al(16384) Bh(8192) Bl(8192) = 49152
// ============================================================================
#define BUFSZ  49152
#define OF_AL  16384
#define OF_BH  32768
#define OF_BL  40960
#define S1_D1  98304
#define S1_D2  102400
#define S1_SM  102656

__global__ void __launch_bounds__(256, 2)
kJ1m(const float* __restrict__ gw0)
{
    extern __shared__ char smraw[];
    uint32_t sb = smem_u32(smraw);
    const int b = blockIdx.y, jt = blockIdx.x * 64;
    const int tid = threadIdx.x, lane = tid & 31, wid = tid >> 5;
    const int m0 = (wid & 3) * 32, n0 = (wid >> 2) * 32;

    float* d1s = (float*)(smraw + S1_D1);
    float* d2s = (float*)(smraw + S1_D2);
    {
        const float* h1b = g_h1 + (size_t)b * 1024;
        for (int i = tid; i < 1024; i += 256) { float h = h1b[i]; d1s[i] = 1.f - h * h; }
        const float* h2b = g_h2 + (size_t)b * 960 + jt;
        if (tid < 64) { float h = h2b[tid]; d2s[tid] = 1.f - h * h; }
    }
    __syncthreads();

    float acc[2][4][4] = {};

    // per-thread ldmatrix address pieces
    const int arow = m0 + (lane & 15);
    const uint32_t aoff = (uint32_t)arow * 128;
    const uint32_t axor = (uint32_t)(arow & 7) << 4;
    const uint32_t asel = (uint32_t)(lane >> 4) << 4;
    const int brow = n0 + lane;
    const uint32_t boff = (uint32_t)brow * 128;
    const uint32_t bxor = (uint32_t)(brow & 7) << 4;

    // prefetch + convert chunk 0 into buf 0
    #define S1_PREF(cc, bufbase)                                                   \
    {                                                                              \
        const int k0 = (cc) * 64;                                                  \
        const char* sH = (const char*)(g_b1h + ((size_t)(cc) * 960 + jt) * 64);    \
        const char* sL = (const char*)(g_b1l + ((size_t)(cc) * 960 + jt) * 64);    \
        for (int off = tid * 16; off < 8192; off += 4096) {                        \
            cpa16((bufbase) + OF_BH + off, sH + off);                              \
            cpa16((bufbase) + OF_BL + off, sL + off);                              \
        }                                                                          \
        CP_COMMIT();                                                               \
        char* Ah = smraw + ((bufbase) - sb);                                       \
        char* Al = Ah + OF_AL;                                                     \
        _Pragma("unroll")                                                          \
        for (int q = 0; q < 8; q++) {                                              \
            int idx = q * 256 + tid;                                               \
            int i = idx >> 4, kq = (idx & 15) << 2;                                \
            float4 gv = make_float4(0.f, 0.f, 0.f, 0.f);                           \
            if (i < 127) gv = *(const float4*)(gw0 + ((size_t)(i + 1) << 10) + k0 + kq); \
            float4 dv = *(const float4*)&d1s[k0 + kq];                             \
            uint2 hw, lw;                                                          \
            split2(gv.x * dv.x, gv.y * dv.y, hw.x, lw.x);                          \
            split2(gv.z * dv.z, gv.w * dv.w, hw.y, lw.y);                          \
            int off = i * 128 + ((kq * 2) ^ ((i & 7) << 4));                       \
            *(uint2*)(Ah + off) = hw;                                              \
            *(uint2*)(Al + off) = lw;                                              \
        }                                                                          \
    }

    S1_PREF(0, sb)

    for (int c = 0; c < 16; c++) {
        const uint32_t cur = sb + (uint32_t)(c & 1) * BUFSZ;
        const uint32_t nxt = sb + (uint32_t)((c + 1) & 1) * BUFSZ;
        if (c + 1 < 16) { S1_PREF(c + 1, nxt) CP_WAIT(1); }
        else            { CP_WAIT(0); }
        __syncthreads();
        #pragma unroll
        for (int ks = 0; ks < 4; ks++) {
            uint32_t ah0[4], ah1[4], al0[4], al1[4];
            uint32_t bh0[4], bh1[4], bl0[4], bl1[4];
            uint32_t ablk = (((uint32_t)(ks * 2) << 4) + asel) ^ axor;
            ldm_x4(ah0, cur + aoff + ablk);
            ldm_x4(ah1, cur + aoff + 2048 + ablk);
            ldm_x4(al0, cur + OF_AL + aoff + ablk);
            ldm_x4(al1, cur + OF_AL + aoff + 2048 + ablk);
            uint32_t b0 = ((uint32_t)(ks * 2) << 4) ^ bxor;
            uint32_t b1 = ((uint32_t)(ks * 2 + 1) << 4) ^ bxor;
            ldm_x4(bh0, cur + OF_BH + boff + b0);
            ldm_x4(bh1, cur + OF_BH + boff + b1);
            ldm_x4(bl0, cur + OF_BL + boff + b0);
            ldm_x4(bl1, cur + OF_BL + boff + b1);
            #pragma unroll
            for (int n = 0; n < 4; n++) { mma16816(acc[0][n], ah0, bh0[n], bh1[n]);
                                          mma16816(acc[1][n], ah1, bh0[n], bh1[n]); }
            #pragma unroll
            for (int n = 0; n < 4; n++) { mma16816(acc[0][n], ah0, bl0[n], bl1[n]);
                                          mma16816(acc[1][n], ah1, bl0[n], bl1[n]); }
            #pragma unroll
            for (int n = 0; n < 4; n++) { mma16816(acc[0][n], al0, bh0[n], bh1[n]);
                                          mma16816(acc[1][n], al1, bh0[n], bh1[n]); }
        }
        __syncthreads();
    }

    // epilogue: *d2[j], pack, store [b][i][j]
    const int g = lane >> 2, tig = lane & 3;
    unsigned int* outb = g_t2p + (size_t)b * 122880;
    #pragma unroll
    for (int mi = 0; mi < 2; mi++) {
        #pragma unroll
        for (int n = 0; n < 4; n++) {
            int lj = n0 + n * 8 + tig * 2;
            int jg = jt + lj;
            float dA = d2s[lj], dB = d2s[lj + 1];
            int i0 = m0 + mi * 16 + g;
            uint2 w0, w1;
            w0.x = pack_hilo(acc[mi][n][0] * dA);
            w0.y = pack_hilo(acc[mi][n][1] * dB);
            w1.x = pack_hilo(acc[mi][n][2] * dA);
            w1.y = pack_hilo(acc[mi][n][3] * dB);
            *(uint2*)(outb + (size_t)i0 * 960 + jg) = w0;
            *(uint2*)(outb + (size_t)(i0 + 8) * 960 + jg) = w1;
        }
    }
}

// ============================================================================
// Stage 2 (mma.sync): t3[i,c] = sum_j t2[b,i,j]*gw2[j,c]; trace in epilogue
// grid (14, 1024): 64-wide c tiles. K = 960 = 15 chunks of 64.
// ============================================================================
#define S2_D3  98304
#define S2_RED 98560
#define S2_SM  99584

__global__ void __launch_bounds__(256, 2)
kJ2m(const float* __restrict__ gdw)
{
    extern __shared__ char smraw[];
    uint32_t sb = smem_u32(smraw);
    const int b = blockIdx.y, ct = blockIdx.x * 64;
    const int tid = threadIdx.x, lane = tid & 31, wid = tid >> 5;
    const int m0 = (wid & 3) * 32, n0 = (wid >> 2) * 32;

    float* d3s = (float*)(smraw + S2_D3);
    if (tid < 64) { float h = g_h3[(size_t)b * 896 + ct + tid]; d3s[tid] = 1.f - h * h; }
    __syncthreads();

    const unsigned int* t2b = g_t2p + (size_t)b * 122880;
    float acc[2][4][4] = {};

    const int arow = m0 + (lane & 15);
    const uint32_t aoff = (uint32_t)arow * 128;
    const uint32_t axor = (uint32_t)(arow & 7) << 4;
    const uint32_t asel = (uint32_t)(lane >> 4) << 4;
    const int brow = n0 + lane;
    const uint32_t boff = (uint32_t)brow * 128;
    const uint32_t bxor = (uint32_t)(brow & 7) << 4;

    #define S2_PREF(cc, bufbase)                                                   \
    {                                                                              \
        const int k0 = (cc) * 64;                                                  \
        const char* sH = (const char*)(g_b2h + ((size_t)(cc) * 896 + ct) * 64);    \
        const char* sL = (const char*)(g_b2l + ((size_t)(cc) * 896 + ct) * 64);    \
        for (int off = tid * 16; off < 8192; off += 4096) {                        \
            cpa16((bufbase) + OF_BH + off, sH + off);                              \
            cpa16((bufbase) + OF_BL + off, sL + off);                              \
        }                                                                          \
        CP_COMMIT();                                                               \
        char* Ah = smraw + ((bufbase) - sb);                                       \
        char* Al = Ah + OF_AL;                                                     \
        _Pragma("unroll")                                                          \
        for (int q = 0; q < 16; q++) {                                             \
            int idx = q * 256 + tid;                                               \
            int i = idx >> 5, kk2 = (idx & 31) * 2;                                \
            uint2 w = *(const uint2*)(t2b + (size_t)i * 960 + k0 + kk2);           \
            uint32_t hv = (w.x & 0xFFFFu) | (w.y << 16);                           \
            uint32_t lv = (w.x >> 16) | (w.y & 0xFFFF0000u);                       \
            int off = i * 128 + ((kk2 * 2) ^ ((i & 7) << 4));                      \
            *(uint32_t*)(Ah + off) = hv;                                           \
            *(uint32_t*)(Al + off) = lv;                                           \
        }                                                                          \
    }

    S2_PREF(0, sb)

    for (int c = 0; c < 15; c++) {
        const uint32_t cur = sb + (uint32_t)(c & 1) * BUFSZ;
        const uint32_t nxt = sb + (uint32_t)((c + 1) & 1) * BUFSZ;
        if (c + 1 < 15) { S2_PREF(c + 1, nxt) CP_WAIT(1); }
        else            { CP_WAIT(0); }
        __syncthreads();
        #pragma unroll
        for (int ks = 0; ks < 4; ks++) {
            uint32_t ah0[4], ah1[4], al0[4], al1[4];
            uint32_t bh0[4], bh1[4], bl0[4], bl1[4];
            uint32_t ablk = (((uint32_t)(ks * 2) << 4) + asel) ^ axor;
            ldm_x4(ah0, cur + aoff + ablk);
            ldm_x4(ah1, cur + aoff + 2048 + ablk);
            ldm_x4(al0, cur + OF_AL + aoff + ablk);
            ldm_x4(al1, cur + OF_AL + aoff + 2048 + ablk);
            uint32_t b0 = ((uint32_t)(ks * 2) << 4) ^ bxor;
            uint32_t b1 = ((uint32_t)(ks * 2 + 1) << 4) ^ bxor;
            ldm_x4(bh0, cur + OF_BH + boff + b0);
            ldm_x4(bh1, cur + OF_BH + boff + b1);
            ldm_x4(bl0, cur + OF_BL + boff + b0);
            ldm_x4(bl1, cur + OF_BL + boff + b1);
            #pragma unroll
            for (int n = 0; n < 4; n++) { mma16816(acc[0][n], ah0, bh0[n], bh1[n]);
                                          mma16816(acc[1][n], ah1, bh0[n], bh1[n]); }
            #pragma unroll
            for (int n = 0; n < 4; n++) { mma16816(acc[0][n], ah0, bl0[n], bl1[n]);
                                          mma16816(acc[1][n], ah1, bl0[n], bl1[n]); }
            #pragma unroll
            for (int n = 0; n < 4; n++) { mma16816(acc[0][n], al0, bh0[n], bh1[n]);
                                          mma16816(acc[1][n], al1, bh0[n], bh1[n]); }
        }
        __syncthreads();
    }

    // epilogue: s += D[i,c] * d3[c] * gdw[c,i]
    const int g = lane >> 2, tig = lane & 3;
    float s = 0.f;
    #pragma unroll
    for (int mi = 0; mi < 2; mi++) {
        #pragma unroll
        for (int n = 0; n < 4; n++) {
            int lc = n0 + n * 8 + tig * 2;
            int c0 = ct + lc;
            float dA = d3s[lc], dB = d3s[lc + 1];
            int i0 = m0 + mi * 16 + g;
            s += acc[mi][n][0] * dA * gdw[(size_t)c0 * 128 + i0];
            s += acc[mi][n][1] * dB * gdw[(size_t)(c0 + 1) * 128 + i0];
            s += acc[mi][n][2] * dA * gdw[(size_t)c0 * 128 + i0 + 8];
            s += acc[mi][n][3] * dB * gdw[(size_t)(c0 + 1) * 128 + i0 + 8];
        }
    }
    // reduce
    #pragma unroll
    for (int o = 16; o > 0; o >>= 1) s += __shfl_xor_sync(0xFFFFFFFFu, s, o);
    float* red = (float*)(smraw + S2_RED);
    if (lane == 0) red[wid] = s;
    __syncthreads();
    if (tid == 0) {
        float t = 0.f;
        #pragma unroll
        for (int w = 0; w < 8; w++) t += red[w];
        g_trp[b * 16 + blockIdx.x] = t;
    }
}

// ---------------- small tail kernels ----------------
__global__ void kGemv(const float* __restrict__ bdw, const float* __restrict__ bdb,
                      float* __restrict__ out)
{
    int b = blockIdx.x, tid = threadIdx.x;
    const float* e = g_e2 + (size_t)b * 448;
    float s = 0.f;
    for (int k = tid; k < 448; k += 128) s += e[k] * bdw[k];
    __shared__ float red[128];
    red[tid] = s;
    __syncthreads();
    for (int st = 64; st > 0; st >>= 1) {
        if (tid < st) red[tid] += red[tid + st];
        __syncthreads();
    }
    if (tid == 0) {
        float gv = red[0] + bdb[0];
        g_gv[b] = gv;
        out[131072 + b] = gv;
    }
}
__global__ void kFinal(const float* __restrict__ p, float* __restrict__ out)
{
    int b = blockIdx.x * blockDim.x + threadIdx.x;
    if (b >= BATCH) return;
    float tr = 0.f;
    #pragma unroll
    for (int t = 0; t < 14; t++) tr += g_trp[b * 16 + t];
    out[132096 + b] = g_gv[b] - p[b] * tr;
}

// ---------------- launch ----------------
extern "C" void kernel_launch(void* const* d_in, const int* in_sizes, int n_in,
                              void* d_out, int out_size)
{
    const float* t   = (const float*)d_in[0];
    const float* x   = (const float*)d_in[1];
    const float* p   = (const float*)d_in[3];
    const float* gw0 = (const float*)d_in[4];
    const float* gb0 = (const float*)d_in[5];
    const float* gw1 = (const float*)d_in[6];
    const float* gb1 = (const float*)d_in[7];
    const float* gw2 = (const float*)d_in[8];
    const float* gb2 = (const float*)d_in[9];
    const float* gdw = (const float*)d_in[10];
    const float* gdb = (const float*)d_in[11];
    const float* bw0 = (const float*)d_in[12];
    const float* bb0 = (const float*)d_in[13];
    const float* bw1 = (const float*)d_in[14];
    const float* bb1 = (const float*)d_in[15];
    const float* bdw = (const float*)d_in[16];
    const float* bdb = (const float*)d_in[17];
    float* out = (float*)d_out;

    cudaFuncSetAttribute(kJ1m, cudaFuncAttributeMaxDynamicSharedMemorySize, S1_SM);
    cudaFuncSetAttribute(kJ2m, cudaFuncAttributeMaxDynamicSharedMemorySize, S2_SM);

    float *st, *h1, *h2, *h3, *e1, *e2;
    cudaGetSymbolAddress((void**)&st, g_st);
    cudaGetSymbolAddress((void**)&h1, g_h1);
    cudaGetSymbolAddress((void**)&h2, g_h2);
    cudaGetSymbolAddress((void**)&h3, g_h3);
    cudaGetSymbolAddress((void**)&e1, g_e1);
    cudaGetSymbolAddress((void**)&e2, g_e2);

    k_build<<<(BATCH * 129 + 255) / 256, 256>>>(t, x);
    kPrepB1<<<(16 * 960 * 64 + 255) / 256, 256>>>(gw1);
    kPrepB2<<<(15 * 896 * 64 + 255) / 256, 256>>>(gw2);

    gemm64<1><<<dim3(16, 16), 256>>>(st, 129, gw0, gb0, h1, 1024, 1024, 1024, 128);
    gemm64<1><<<dim3(15, 16), 256>>>(h1, 1024, gw1, gb1, h2, 960, 1024, 960, 1024);
    gemm64<1><<<dim3(14, 16), 256>>>(h2, 960, gw2, gb2, h3, 896, 1024, 896, 960);
    gemm64<0><<<dim3(2, 16), 256>>>(h3, 896, gdw, gdb, out, 128, 1024, 128, 896);
    gemm64<1><<<dim3(8, 16), 256>>>(st, 129, bw0, bb0, e1, 512, 1024, 512, 129);
    gemm64<1><<<dim3(7, 16), 256>>>(e1, 512, bw1, bb1, e2, 448, 1024, 448, 512);
    kGemv<<<BATCH, 128>>>(bdw, bdb, out);

    kJ1m<<<dim3(15, BATCH), 256, S1_SM>>>(gw0);
    kJ2m<<<dim3(14, BATCH), 256, S2_SM>>>(gdw);
    kFinal<<<4, 256>>>(p, out);

    (void)in_sizes; (void)n_in; (void)out_size;
}